// round 13
// baseline (speedup 1.0000x reference)
#include <cuda_runtime.h>
#include <math.h>

#define NN   512
#define DD   128
#define M_TOTAL 2048   // 4*512

// Scratch (device globals: no allocation allowed in kernel_launch)
__device__ float g_Pb[M_TOTAL * DD];   // x@W1 - x@W2 + bias
__device__ float g_Q [M_TOTAL * DD];   // x@W2
__device__ unsigned long long g_keys[4 * NN * DD];  // 2 MB sorted (val|idx) keys

typedef unsigned long long ull;

static __device__ __forceinline__ ull pk2(float a) {      // {a, a}
    ull r; unsigned ai = __float_as_uint(a);
    asm("mov.b64 %0, {%1, %1};" : "=l"(r) : "r"(ai));
    return r;
}
static __device__ __forceinline__ ull fma2(ull a, ull b, ull c) {
    ull r; asm("fma.rn.f32x2 %0, %1, %2, %3;" : "=l"(r) : "l"(a), "l"(b), "l"(c));
    return r;
}

union U2F2 { ull u; float2 f2; };

// ---------------- cp.async helpers ----------------
static __device__ __forceinline__ void cpasync16(unsigned dst, const void* src) {
    asm volatile("cp.async.cg.shared.global [%0], [%1], 16;"
                 :: "r"(dst), "l"(src));
}
#define CP_COMMIT() asm volatile("cp.async.commit_group;")
#define CP_WAIT(n)  asm volatile("cp.async.wait_group %0;" :: "n"(n))

// ---------------------------------------------------------------------------
// Kernel 1: fused dual GEMM, W staged in SMEM (unchanged from R11).
// ---------------------------------------------------------------------------
__global__ __launch_bounds__(256)
void ec_gemm_kernel(const float* __restrict__ x,
                    const float* __restrict__ W,
                    const float* __restrict__ bias) {
    __shared__ ull xs[16 * DD];        // 16 KB: {x,x} per (row, k)
    __shared__ ull wb[2][16 * 128];    // 32 KB

    const int tid  = threadIdx.x;
    const int w    = tid >> 5;
    const int lane = tid & 31;
    const int rowBase = blockIdx.x * 16;

    const int ch  = w & 1;
    const int r0  = (w >> 1) * 4;
    const int cp  = ch * 32 + lane;

    const float4* __restrict__ W4 = (const float4*)W;

    {
        unsigned dst = (unsigned)__cvta_generic_to_shared(&wb[0][0]);
#pragma unroll
        for (int t = 0; t < 4; ++t) {
            const int idx = tid + t * 256;
            const int half = idx >> 9;
            const int i2 = idx & 511;
            const int k = i2 >> 5, l = i2 & 31;
            cpasync16(dst + (k * 64 + half * 32 + l) * 16,
                      W4 + (size_t)(k + half * DD) * 32 + l);
        }
        CP_COMMIT();
    }

    {
        const float4* x4 = (const float4*)(x + (size_t)rowBase * DD);
#pragma unroll
        for (int t = 0; t < 2; ++t) {
            const int idx = tid + t * 256;
            const float4 f = __ldg(&x4[idx]);
            xs[idx * 4 + 0] = pk2(f.x);
            xs[idx * 4 + 1] = pk2(f.y);
            xs[idx * 4 + 2] = pk2(f.z);
            xs[idx * 4 + 3] = pk2(f.w);
        }
    }

    ull a1[4], qq[4];
#pragma unroll
    for (int r = 0; r < 4; ++r) { a1[r] = 0ull; qq[r] = 0ull; }

    for (int c = 0; c < 8; ++c) {
        const int kc = c * 16;
        if (c < 7) {
            unsigned dst = (unsigned)__cvta_generic_to_shared(&wb[(c + 1) & 1][0]);
            const int kn = kc + 16;
#pragma unroll
            for (int t = 0; t < 4; ++t) {
                const int idx = tid + t * 256;
                const int half = idx >> 9;
                const int i2 = idx & 511;
                const int k = i2 >> 5, l = i2 & 31;
                cpasync16(dst + (k * 64 + half * 32 + l) * 16,
                          W4 + (size_t)(kn + k + half * DD) * 32 + l);
            }
            CP_COMMIT();
            CP_WAIT(1);
        } else {
            CP_WAIT(0);
        }
        __syncthreads();

        const ull* wc = &wb[c & 1][0];
#pragma unroll
        for (int k = 0; k < 16; ++k) {
            const ull w1 = wc[k * 128 + cp];
            const ull w2 = wc[k * 128 + 64 + cp];
#pragma unroll
            for (int r = 0; r < 4; ++r) {
                const ull xp = xs[(r0 + r) * DD + kc + k];
                a1[r] = fma2(xp, w1, a1[r]);
                qq[r] = fma2(xp, w2, qq[r]);
            }
        }
        __syncthreads();
    }

    const float2 b2 = __ldg(&((const float2*)bias)[cp]);
#pragma unroll
    for (int r = 0; r < 4; ++r) {
        U2F2 A, Q;
        A.u = a1[r]; Q.u = qq[r];
        float2 P;
        P.x = (A.f2.x - Q.f2.x) + b2.x;
        P.y = (A.f2.y - Q.f2.y) + b2.y;
        const int m = rowBase + r0 + r;
        ((float2*)g_Pb)[(size_t)m * 64 + cp] = P;
        ((float2*)g_Q )[(size_t)m * 64 + cp] = Q.f2;
    }
}

// ---------------------------------------------------------------------------
// Kernel 2: per-(b,o)-column descending sort of Q values (bitonic, 1 warp).
// Key = orderable(f32) << 32 | j  -> exact value recoverable from key.
// grid 512 x 32 threads: column c -> b = c>>7, o = c&127.
// ---------------------------------------------------------------------------
__global__ __launch_bounds__(32)
void ec_sort_kernel() {
    __shared__ ull s[NN];

    const int lane = threadIdx.x;
    const int col  = blockIdx.x;
    const int b    = col >> 7;
    const int o    = col & 127;

    const float* __restrict__ Qc = g_Q + (size_t)b * NN * DD + o;

    // load + orderable transform (desc sort of u64 == desc sort of float)
#pragma unroll
    for (int t = 0; t < 16; ++t) {
        const int j = t * 32 + lane;
        const unsigned fb = __float_as_uint(__ldg(Qc + (size_t)j * DD));
        const unsigned u = (fb & 0x80000000u) ? ~fb : (fb | 0x80000000u);
        s[j] = ((ull)u << 32) | (unsigned)j;
    }
    __syncwarp();

    for (int k = 2; k <= NN; k <<= 1) {
        for (int j = k >> 1; j > 0; j >>= 1) {
#pragma unroll
            for (int p = 0; p < 8; ++p) {
                const int t = p * 32 + lane;
                const int i = ((t & ~(j - 1)) << 1) | (t & (j - 1));
                const int q = i | j;
                const ull a = s[i];
                const ull c = s[q];
                const bool up = (i & k) == 0;       // descending segments
                const bool sw = up ? (a < c) : (a > c);
                if (sw) { s[i] = c; s[q] = a; }
            }
            __syncwarp();
        }
    }

    ull* __restrict__ Kc = g_keys + (size_t)b * NN * DD + o;
#pragma unroll
    for (int t = 0; t < 16; ++t) {
        const int k = t * 32 + lane;
        Kc[(size_t)k * DD] = s[k];
    }
}

// ---------------------------------------------------------------------------
// Kernel 3: probe — first sorted candidate that is a neighbor == masked max.
//   out[i,o] = max(0, Pb[i,o] + first-hit value)   (exhaustion -> -inf -> 0)
// grid 1024 x 256 threads; block = 2 i-rows x 128 o; warp = (row, 32-o chunk).
// adj rows ballot-packed to bitmasks in smem; keys read coalesced with
// 1-deep prefetch; early exit via __all_sync.
// ---------------------------------------------------------------------------
__global__ __launch_bounds__(256)
void ec_probe_kernel(const float* __restrict__ adj,
                     float* __restrict__ out) {
    __shared__ unsigned bm[2][16];

    const int tid  = threadIdx.x;
    const int w    = tid >> 5;
    const int lane = tid & 31;
    const int i0   = blockIdx.x * 2;

    // pack adj bitmask for the 2 rows (warps 0 and 1)
    if (w < 2) {
        const int row = i0 + w;
#pragma unroll
        for (int wd = 0; wd < 16; ++wd) {
            const float v = __ldg(&adj[(size_t)row * NN + wd * 32 + lane]);
            const unsigned m = __ballot_sync(0xffffffffu, v > 0.0f);
            if (lane == 0) bm[w][wd] = m;
        }
    }
    __syncthreads();

    const int rl   = w >> 2;                // local row 0/1
    const int row  = i0 + rl;
    const int o    = (w & 3) * 32 + lane;
    const int b    = row >> 9;

    const ull* __restrict__ Kc = g_keys + (size_t)b * NN * DD + o;

    float best = -3.0e38f;
    bool  done = false;

    ull nk = __ldg(Kc);                     // prefetch k = 0
    for (int k = 0; k < NN; ++k) {
        const ull key = nk;
        if (k < NN - 1) nk = __ldg(Kc + (size_t)(k + 1) * DD);
        if (!done) {
            const int idx = (int)(key & 511u);
            const unsigned wm = bm[rl][idx >> 5];
            if ((wm >> (idx & 31)) & 1u) {
                const unsigned u = (unsigned)(key >> 32);
                const unsigned fb = (u & 0x80000000u) ? (u ^ 0x80000000u) : ~u;
                best = __uint_as_float(fb);
                done = true;
            }
        }
        if (__all_sync(0xffffffffu, done)) break;
    }

    const float p = __ldg(&g_Pb[(size_t)row * DD + o]);
    out[(size_t)row * DD + o] = fmaxf(0.0f, p + best);
}

// ---------------------------------------------------------------------------
extern "C" void kernel_launch(void* const* d_in, const int* in_sizes, int n_in,
                              void* d_out, int out_size) {
    const float* x    = (const float*)d_in[0];   // (4,512,128)
    const float* adj  = (const float*)d_in[1];   // (4,512,512)
    const float* W    = (const float*)d_in[2];   // (256,128)
    const float* bias = (const float*)d_in[3];   // (128,)
    float*       out  = (float*)d_out;           // (4,512,128)

    ec_gemm_kernel <<<M_TOTAL / 16, 256>>>(x, W, bias);
    ec_sort_kernel <<<4 * DD, 32>>>();
    ec_probe_kernel<<<M_TOTAL / 2, 256>>>(adj, out);
}

// round 14
// speedup vs baseline: 1.3344x; 1.3344x over previous
#include <cuda_runtime.h>
#include <math.h>

#define NN   512
#define DD   128
#define M_TOTAL 2048   // 4*512

// Scratch (device globals: no allocation allowed in kernel_launch)
__device__ float g_Pb[M_TOTAL * DD];   // x@W1 - x@W2 + bias
__device__ float g_Q [M_TOTAL * DD];   // x@W2
__device__ unsigned long long g_keys[4 * NN * DD];  // [b][o][k] sorted desc

typedef unsigned long long ull;

static __device__ __forceinline__ ull pk2(float a) {      // {a, a}
    ull r; unsigned ai = __float_as_uint(a);
    asm("mov.b64 %0, {%1, %1};" : "=l"(r) : "r"(ai));
    return r;
}
static __device__ __forceinline__ ull fma2(ull a, ull b, ull c) {
    ull r; asm("fma.rn.f32x2 %0, %1, %2, %3;" : "=l"(r) : "l"(a), "l"(b), "l"(c));
    return r;
}

union U2F2 { ull u; float2 f2; };

// ---------------- cp.async helpers ----------------
static __device__ __forceinline__ void cpasync16(unsigned dst, const void* src) {
    asm volatile("cp.async.cg.shared.global [%0], [%1], 16;"
                 :: "r"(dst), "l"(src));
}
#define CP_COMMIT() asm volatile("cp.async.commit_group;")
#define CP_WAIT(n)  asm volatile("cp.async.wait_group %0;" :: "n"(n))

// ---------------------------------------------------------------------------
// Kernel 1: fused dual GEMM, column-split for occupancy.
//   A1 = x@W1 ; Q = x@W2 ; Pb = A1 - Q + bias (epilogue)
// grid 256 = (128 row-blocks x 2 col-halves) x 256 threads.
// Block = 16 rows x 64 cols; warp = 2 rows; lane = 1 col-pair of its half.
// W half (64 KB) staged in 4 chunks of 32 k, double-buffered cp.async.
// Total W L2 traffic: 256 blocks x 64 KB = 16 MB.
// ---------------------------------------------------------------------------
__global__ __launch_bounds__(256)
void ec_gemm_kernel(const float* __restrict__ x,
                    const float* __restrict__ W,
                    const float* __restrict__ bias) {
    __shared__ ull xs[16 * DD];          // 16 KB {x,x}
    __shared__ ull wb[2][32 * 64];       // 2 x 16 KB: [k][m*32 + cp]

    const int tid  = threadIdx.x;
    const int w    = tid >> 5;
    const int lane = tid & 31;
    const int rowBase = (blockIdx.x >> 1) * 16;
    const int h    = blockIdx.x & 1;     // col half

    const int r0 = w * 2;

    const float4* __restrict__ W4 = (const float4*)W;

    // stage W chunk 0 (async): 1024 float4 = 32 k x 16 f4 x 2 matrices
    {
        unsigned dst = (unsigned)__cvta_generic_to_shared(&wb[0][0]);
#pragma unroll
        for (int t = 0; t < 4; ++t) {
            const int idx = tid + t * 256;
            const int m  = idx >> 9;             // 0: W1, 1: W2
            const int i2 = idx & 511;
            const int k  = i2 >> 4;
            const int f  = i2 & 15;
            cpasync16(dst + k * 512 + m * 256 + f * 16,
                      W4 + (size_t)(k + m * DD) * 32 + 16 * h + f);
        }
        CP_COMMIT();
    }

    // load & pack x tile: 16 rows x 128 k = 512 float4
    {
        const float4* x4 = (const float4*)(x + (size_t)rowBase * DD);
#pragma unroll
        for (int t = 0; t < 2; ++t) {
            const int idx = tid + t * 256;
            const float4 f = __ldg(&x4[idx]);
            xs[idx * 4 + 0] = pk2(f.x);
            xs[idx * 4 + 1] = pk2(f.y);
            xs[idx * 4 + 2] = pk2(f.z);
            xs[idx * 4 + 3] = pk2(f.w);
        }
    }

    ull a1[2] = {0ull, 0ull};
    ull qq[2] = {0ull, 0ull};

    for (int c = 0; c < 4; ++c) {
        const int kc = c * 32;
        if (c < 3) {       // stage next chunk
            unsigned dst = (unsigned)__cvta_generic_to_shared(&wb[(c + 1) & 1][0]);
            const int kn = kc + 32;
#pragma unroll
            for (int t = 0; t < 4; ++t) {
                const int idx = tid + t * 256;
                const int m  = idx >> 9;
                const int i2 = idx & 511;
                const int k  = i2 >> 4;
                const int f  = i2 & 15;
                cpasync16(dst + k * 512 + m * 256 + f * 16,
                          W4 + (size_t)(kn + k + m * DD) * 32 + 16 * h + f);
            }
            CP_COMMIT();
            CP_WAIT(1);
        } else {
            CP_WAIT(0);
        }
        __syncthreads();

        const ull* wc = &wb[c & 1][0];
#pragma unroll
        for (int k = 0; k < 32; ++k) {
            const ull w1 = wc[k * 64 + lane];        // LDS.64 conflict-free
            const ull w2 = wc[k * 64 + 32 + lane];
#pragma unroll
            for (int r = 0; r < 2; ++r) {
                const ull xp = xs[(r0 + r) * DD + kc + k];   // broadcast
                a1[r] = fma2(xp, w1, a1[r]);
                qq[r] = fma2(xp, w2, qq[r]);
            }
        }
        __syncthreads();
    }

    const int cp = 32 * h + lane;        // global col-pair 0..63
    const float2 b2 = __ldg(&((const float2*)bias)[cp]);
#pragma unroll
    for (int r = 0; r < 2; ++r) {
        U2F2 A, Q;
        A.u = a1[r]; Q.u = qq[r];
        float2 P;
        P.x = (A.f2.x - Q.f2.x) + b2.x;
        P.y = (A.f2.y - Q.f2.y) + b2.y;
        const int m = rowBase + r0 + r;
        ((float2*)g_Pb)[(size_t)m * 64 + cp] = P;
        ((float2*)g_Q )[(size_t)m * 64 + cp] = Q.f2;
    }
}

// ---------------------------------------------------------------------------
// Kernel 2: per-(b,o)-column descending bitonic sort, 256 THREADS PER COLUMN.
// Key = orderable(f32) << 32 | j. grid 512 x 256. Keys stored k-contiguous:
// g_keys[(b*128+o)*512 + k] so probe reads are sequential 16B chunks.
// ---------------------------------------------------------------------------
__global__ __launch_bounds__(256)
void ec_sort_kernel() {
    __shared__ ull s[NN];

    const int tid = threadIdx.x;
    const int col = blockIdx.x;
    const int b   = col >> 7;
    const int o   = col & 127;

    const float* __restrict__ Qc = g_Q + (size_t)b * NN * DD + o;

    // load + orderable transform
#pragma unroll
    for (int t = 0; t < 2; ++t) {
        const int j = tid + t * 256;
        const unsigned fb = __float_as_uint(__ldg(Qc + (size_t)j * DD));
        const unsigned u = (fb & 0x80000000u) ? ~fb : (fb | 0x80000000u);
        s[j] = ((ull)u << 32) | (unsigned)j;
    }
    __syncthreads();

    for (int k = 2; k <= NN; k <<= 1) {
        for (int j = k >> 1; j > 0; j >>= 1) {
            const int i = ((tid & ~(j - 1)) << 1) | (tid & (j - 1));
            const int q = i | j;
            const ull a = s[i];
            const ull c = s[q];
            const bool up = (i & k) == 0;       // descending overall
            const bool sw = up ? (a < c) : (a > c);
            if (sw) { s[i] = c; s[q] = a; }
            __syncthreads();
        }
    }

    ull* __restrict__ Kc = g_keys + ((size_t)col << 9);
    Kc[tid]       = s[tid];          // coalesced
    Kc[tid + 256] = s[tid + 256];
}

// ---------------------------------------------------------------------------
// Kernel 3: probe — first sorted candidate that is a neighbor == masked max.
//   out[i,o] = max(0, Pb[i,o] + first-hit value)  (exhaustion -> -inf -> 0)
// grid 512 x 512 threads; block = 4 i-rows x 128 o; thread = one (i,o).
// Keys read as ulonglong2 (2 keys / 16B); head lines L1-hot (shared by all i).
// Exact: loop runs to k=512 if needed.
// ---------------------------------------------------------------------------
__global__ __launch_bounds__(512)
void ec_probe_kernel(const float* __restrict__ adj,
                     float* __restrict__ out) {
    __shared__ unsigned bm[4][16];

    const int tid  = threadIdx.x;
    const int w    = tid >> 5;
    const int lane = tid & 31;
    const int i0   = blockIdx.x * 4;

    // warps 0..3 pack adj bitmask for rows 0..3
    if (w < 4) {
        const int row = i0 + w;
#pragma unroll
        for (int wd = 0; wd < 16; ++wd) {
            const float v = __ldg(&adj[(size_t)row * NN + wd * 32 + lane]);
            const unsigned m = __ballot_sync(0xffffffffu, v > 0.0f);
            if (lane == 0) bm[w][wd] = m;
        }
    }
    __syncthreads();

    const int rl  = tid >> 7;            // local row 0..3
    const int row = i0 + rl;
    const int o   = tid & 127;
    const int b   = row >> 9;

    const ulonglong2* __restrict__ K2 =
        (const ulonglong2*)(g_keys + ((size_t)(b * DD + o) << 9));

    float best = -3.0e38f;
    for (int c = 0; c < 256; ++c) {
        const ulonglong2 kk = __ldg(K2 + c);
        {
            const int idx = (int)(kk.x & 511u);
            if ((bm[rl][idx >> 5] >> (idx & 31)) & 1u) {
                const unsigned u = (unsigned)(kk.x >> 32);
                const unsigned fb = (u & 0x80000000u) ? (u ^ 0x80000000u) : ~u;
                best = __uint_as_float(fb);
                break;
            }
        }
        {
            const int idx = (int)(kk.y & 511u);
            if ((bm[rl][idx >> 5] >> (idx & 31)) & 1u) {
                const unsigned u = (unsigned)(kk.y >> 32);
                const unsigned fb = (u & 0x80000000u) ? (u ^ 0x80000000u) : ~u;
                best = __uint_as_float(fb);
                break;
            }
        }
    }

    const float p = __ldg(&g_Pb[(size_t)row * DD + o]);
    out[(size_t)row * DD + o] = fmaxf(0.0f, p + best);
}

// ---------------------------------------------------------------------------
extern "C" void kernel_launch(void* const* d_in, const int* in_sizes, int n_in,
                              void* d_out, int out_size) {
    const float* x    = (const float*)d_in[0];   // (4,512,128)
    const float* adj  = (const float*)d_in[1];   // (4,512,512)
    const float* W    = (const float*)d_in[2];   // (256,128)
    const float* bias = (const float*)d_in[3];   // (128,)
    float*       out  = (float*)d_out;           // (4,512,128)

    ec_gemm_kernel <<<256, 256>>>(x, W, bias);
    ec_sort_kernel <<<4 * DD, 256>>>();
    ec_probe_kernel<<<M_TOTAL / 4, 512>>>(adj, out);
}